// round 1
// baseline (speedup 1.0000x reference)
#include <cuda_runtime.h>

// G2InvariantAttention — GB300 sm_103a
// Key simplifications (exact, from the reference math):
//   * oct_cross(k, k) == 0  (antisymmetric structure constants)  -> k_mix = w_k * k
//   * v == k  -> y_v == k_pooled, single attention-weighted sum needed
//   * logit scale w_k/sqrt(7) and log2(e) folded into q; softmax max-subtraction
//     skipped (logits bounded ~17, exp far from fp32 overflow)
//   * K stored in smem padded to 8 floats/key with slot7 = 1.0 so the packed
//     accumulator's 8th lane produces the softmax denominator for free.

#define N_TOK   2048
#define N_HEAD  16
#define N_BATCH 2
#define DMODEL  128
#define TPB     256

typedef unsigned long long u64;

__device__ __forceinline__ u64 f2pack(float lo, float hi) {
    u64 r; asm("mov.b64 %0,{%1,%2};" : "=l"(r) : "f"(lo), "f"(hi)); return r;
}
__device__ __forceinline__ void f2unpack(u64 v, float& lo, float& hi) {
    asm("mov.b64 {%0,%1},%2;" : "=f"(lo), "=f"(hi) : "l"(v));
}
__device__ __forceinline__ u64 f2fma(u64 a, u64 b, u64 c) {
    u64 d; asm("fma.rn.f32x2 %0,%1,%2,%3;" : "=l"(d) : "l"(a), "l"(b), "l"(c)); return d;
}
__device__ __forceinline__ u64 f2mul(u64 a, u64 b) {
    u64 d; asm("mul.rn.f32x2 %0,%1,%2;" : "=l"(d) : "l"(a), "l"(b)); return d;
}
__device__ __forceinline__ float fast_ex2(float x) {
    float r; asm("ex2.approx.f32 %0,%1;" : "=f"(r) : "f"(x)); return r;
}

__global__ void __launch_bounds__(TPB) g2_attn_kernel(
    const float* __restrict__ o, const float* __restrict__ mix,
    const float* __restrict__ alpha, const float* __restrict__ beta,
    float* __restrict__ out)
{
    extern __shared__ float sK[];  // [N_TOK][8] : imag0..6, 1.0f
    const int h = blockIdx.y, b = blockIdx.z;
    const int tid = threadIdx.x;
    const float* obase = o + ((size_t)b * N_TOK) * DMODEL + h * 8;

    // Cooperative load of the full K tile for this (b,h) into smem.
    for (int j = tid; j < N_TOK; j += TPB) {
        float4 v0 = *(const float4*)(obase + (size_t)j * DMODEL);      // real, i0,i1,i2
        float4 v1 = *(const float4*)(obase + (size_t)j * DMODEL + 4);  // i3..i6
        *(float4*)(sK + j * 8)     = make_float4(v0.y, v0.z, v0.w, v1.x);
        *(float4*)(sK + j * 8 + 4) = make_float4(v1.y, v1.z, v1.w, 1.0f);
    }
    __syncthreads();

    const int n = blockIdx.x * TPB + tid;

    // w_k = softmax(mix[h])[0] = sigmoid(m0 - m1); fold scale + log2e into q.
    float m0 = mix[2 * h], m1 = mix[2 * h + 1];
    float wk = 1.0f / (1.0f + __expf(m1 - m0));
    const float coef = wk * 1.4426950408889634f * 0.3779644730092272f;  // *log2e/sqrt(7)

    float qo[7];
    #pragma unroll
    for (int i = 0; i < 7; i++) qo[i] = sK[n * 8 + i];
    u64 q01 = f2pack(qo[0] * coef, qo[1] * coef);
    u64 q23 = f2pack(qo[2] * coef, qo[3] * coef);
    u64 q45 = f2pack(qo[4] * coef, qo[5] * coef);
    u64 q67 = f2pack(qo[6] * coef, 0.0f);  // pad lane: q7 = 0 so K's 1.0 pad doesn't affect score

    u64 a01 = 0ULL, a23 = 0ULL, a45 = 0ULL, a67 = 0ULL;  // a67.hi accumulates sum(exp) = l

    unsigned sbase;
    asm("{ .reg .u64 t; cvta.to.shared.u64 t, %1; cvt.u32.u64 %0, t; }"
        : "=r"(sbase) : "l"(sK));

    unsigned addr = sbase;
    #pragma unroll 4
    for (int j = 0; j < N_TOK; j++, addr += 32) {
        u64 K01, K23, K45, K67;
        asm("ld.shared.v2.b64 {%0,%1},[%2];" : "=l"(K01), "=l"(K23) : "r"(addr));
        asm("ld.shared.v2.b64 {%0,%1},[%2];" : "=l"(K45), "=l"(K67) : "r"(addr + 16));
        u64 s2 = f2mul(q01, K01);
        s2 = f2fma(q23, K23, s2);
        s2 = f2fma(q45, K45, s2);
        s2 = f2fma(q67, K67, s2);
        float sl, sh; f2unpack(s2, sl, sh);
        float e = fast_ex2(sl + sh);       // exp2 of pre-scaled logit
        u64 e2 = f2pack(e, e);
        a01 = f2fma(K01, e2, a01);
        a23 = f2fma(K23, e2, a23);
        a45 = f2fma(K45, e2, a45);
        a67 = f2fma(K67, e2, a67);
    }

    float y[7], l;
    f2unpack(a01, y[0], y[1]);
    f2unpack(a23, y[2], y[3]);
    f2unpack(a45, y[4], y[5]);
    f2unpack(a67, y[6], l);
    float rinv;
    asm("rcp.approx.f32 %0,%1;" : "=f"(rinv) : "f"(l));
    #pragma unroll
    for (int i = 0; i < 7; i++) y[i] *= rinv;

    // Octonion cross product c = qo x y (21 antisymmetric terms).
    float c[7];
    #pragma unroll
    for (int i = 0; i < 7; i++) c[i] = 0.0f;
    const int FI[7] = {0, 0, 0, 1, 1, 2, 2};
    const int FJ[7] = {1, 3, 6, 3, 4, 3, 5};
    const int FK[7] = {2, 4, 5, 5, 6, 6, 4};
    #pragma unroll
    for (int t = 0; t < 7; t++) {
        int i = FI[t], j = FJ[t], k = FK[t];
        c[k] += qo[i] * y[j] - qo[j] * y[i];
        c[i] += qo[j] * y[k] - qo[k] * y[j];
        c[j] += qo[k] * y[i] - qo[i] * y[k];
    }

    float av = 1.0f / (1.0f + __expf(-alpha[h]));
    float bv = tanhf(beta[h]);

    float real = obase[(size_t)n * DMODEL];  // component 0 passes through
    float im[7];
    float ns = real * real;
    #pragma unroll
    for (int i = 0; i < 7; i++) {
        im[i] = av * y[i] + bv * c[i];
        ns += im[i] * im[i];
    }
    float nrm = sqrtf(ns);
    float inv = 1.0f / fmaxf(nrm, 1e-12f);

    float* op = out + ((size_t)(b * N_TOK + n)) * DMODEL + h * 8;
    *(float4*)(op)     = make_float4(real * inv, im[0] * inv, im[1] * inv, im[2] * inv);
    *(float4*)(op + 4) = make_float4(im[3] * inv, im[4] * inv, im[5] * inv, im[6] * inv);
}

extern "C" void kernel_launch(void* const* d_in, const int* in_sizes, int n_in,
                              void* d_out, int out_size) {
    const float* o     = (const float*)d_in[0];
    const float* mix   = (const float*)d_in[1];
    const float* alpha = (const float*)d_in[2];
    const float* beta  = (const float*)d_in[3];
    float* out = (float*)d_out;

    (void)in_sizes; (void)n_in; (void)out_size;

    cudaFuncSetAttribute(g2_attn_kernel,
                         cudaFuncAttributeMaxDynamicSharedMemorySize,
                         N_TOK * 8 * (int)sizeof(float));

    dim3 grid(N_TOK / TPB, N_HEAD, N_BATCH);  // (8, 16, 2) = 256 CTAs, all resident
    g2_attn_kernel<<<grid, TPB, N_TOK * 8 * sizeof(float)>>>(o, mix, alpha, beta, out);
}

// round 2
// speedup vs baseline: 1.2412x; 1.2412x over previous
#include <cuda_runtime.h>

// G2InvariantAttention — GB300 sm_103a — Round 2: split-K for occupancy.
// Math simplifications (exact):
//   * oct_cross(k,k)==0 -> k_mix = w_k * k ; v==k -> single weighted sum
//   * logit scale w_k*log2e/sqrt(7) folded into q; no max-subtraction needed
//     (logits bounded ~17), so exp-weighted partials over key slices combine
//     LINEARLY -> split-K across CTAs with a trivial sum-combine kernel.
//   * K padded to 8 floats/key with slot7=1.0 so packed accumulator lane 7
//     yields the softmax denominator l for free.

#define N_TOK   2048
#define N_HEAD  16
#define N_BATCH 2
#define DMODEL  128
#define TPB     256
#define KSPLIT  4
#define KCHUNK  (N_TOK / KSPLIT)   // 512 keys per CTA

typedef unsigned long long u64;

// Scratch: [KSPLIT][B*H][N][8] partial accumulators = 8 MB
__device__ u64 g_part[(size_t)KSPLIT * N_BATCH * N_HEAD * N_TOK * 4];

__device__ __forceinline__ u64 f2pack(float lo, float hi) {
    u64 r; asm("mov.b64 %0,{%1,%2};" : "=l"(r) : "f"(lo), "f"(hi)); return r;
}
__device__ __forceinline__ void f2unpack(u64 v, float& lo, float& hi) {
    asm("mov.b64 {%0,%1},%2;" : "=f"(lo), "=f"(hi) : "l"(v));
}
__device__ __forceinline__ u64 f2fma(u64 a, u64 b, u64 c) {
    u64 d; asm("fma.rn.f32x2 %0,%1,%2,%3;" : "=l"(d) : "l"(a), "l"(b), "l"(c)); return d;
}
__device__ __forceinline__ u64 f2mul(u64 a, u64 b) {
    u64 d; asm("mul.rn.f32x2 %0,%1,%2;" : "=l"(d) : "l"(a), "l"(b)); return d;
}
__device__ __forceinline__ float fast_ex2(float x) {
    float r; asm("ex2.approx.f32 %0,%1;" : "=f"(r) : "f"(x)); return r;
}

// ---------------- Kernel 1: partial attention sums over a 512-key slice ----
__global__ void __launch_bounds__(TPB) g2_attn_partial(
    const float* __restrict__ o, const float* __restrict__ mix)
{
    __shared__ float sK[KCHUNK * 8];   // 16 KB

    const int bh  = blockIdx.y;            // b*16 + h
    const int h   = bh & (N_HEAD - 1);
    const int b   = bh >> 4;
    const int ks  = blockIdx.z;
    const int tid = threadIdx.x;
    const float* obase = o + ((size_t)b * N_TOK) * DMODEL + h * 8;

    // Load this CTA's key slice (512 keys x 8 floats) into smem.
    #pragma unroll
    for (int r = 0; r < KCHUNK / TPB; r++) {
        int j  = r * TPB + tid;
        int jg = ks * KCHUNK + j;
        float4 v0 = *(const float4*)(obase + (size_t)jg * DMODEL);
        float4 v1 = *(const float4*)(obase + (size_t)jg * DMODEL + 4);
        *(float4*)(sK + j * 8)     = make_float4(v0.y, v0.z, v0.w, v1.x);
        *(float4*)(sK + j * 8 + 4) = make_float4(v1.y, v1.z, v1.w, 1.0f);
    }
    __syncthreads();

    const int n = blockIdx.x * TPB + tid;

    // w_k = sigmoid(m0-m1); fold w_k * log2e / sqrt(7) into q.
    float m0 = mix[2 * h], m1 = mix[2 * h + 1];
    float wk = 1.0f / (1.0f + __expf(m1 - m0));
    const float coef = wk * 1.4426950408889634f * 0.3779644730092272f;

    // Load q from global (its row may not be in this CTA's key slice).
    float4 q0 = *(const float4*)(obase + (size_t)n * DMODEL);      // real,i0,i1,i2
    float4 q1 = *(const float4*)(obase + (size_t)n * DMODEL + 4);  // i3..i6
    u64 q01 = f2pack(q0.y * coef, q0.z * coef);
    u64 q23 = f2pack(q0.w * coef, q1.x * coef);
    u64 q45 = f2pack(q1.y * coef, q1.z * coef);
    u64 q67 = f2pack(q1.w * coef, 0.0f);   // lane7 = 0: K pad doesn't affect score

    u64 a01 = 0ULL, a23 = 0ULL, a45 = 0ULL, a67 = 0ULL;  // a67.hi = sum(exp)

    unsigned sbase;
    asm("{ .reg .u64 t; cvta.to.shared.u64 t, %1; cvt.u32.u64 %0, t; }"
        : "=r"(sbase) : "l"(sK));

    unsigned addr = sbase;
    #pragma unroll 8
    for (int j = 0; j < KCHUNK; j++, addr += 32) {
        u64 K01, K23, K45, K67;
        asm("ld.shared.v2.b64 {%0,%1},[%2];" : "=l"(K01), "=l"(K23) : "r"(addr));
        asm("ld.shared.v2.b64 {%0,%1},[%2];" : "=l"(K45), "=l"(K67) : "r"(addr + 16));
        u64 s2 = f2mul(q01, K01);
        s2 = f2fma(q23, K23, s2);
        s2 = f2fma(q45, K45, s2);
        s2 = f2fma(q67, K67, s2);
        float sl, sh; f2unpack(s2, sl, sh);
        float e = fast_ex2(sl + sh);
        u64 e2 = f2pack(e, e);
        a01 = f2fma(K01, e2, a01);
        a23 = f2fma(K23, e2, a23);
        a45 = f2fma(K45, e2, a45);
        a67 = f2fma(K67, e2, a67);
    }

    // Write partial (y0..y6, l) — 32 bytes.
    u64* p = g_part + ((((size_t)ks * (N_BATCH * N_HEAD) + bh) * N_TOK + n) << 2);
    ulonglong2 w0; w0.x = a01; w0.y = a23;
    ulonglong2 w1; w1.x = a45; w1.y = a67;
    *(ulonglong2*)(p)     = w0;
    *(ulonglong2*)(p + 2) = w1;
}

// ---------------- Kernel 2: combine partials + epilogue ---------------------
__global__ void __launch_bounds__(TPB) g2_attn_combine(
    const float* __restrict__ o,
    const float* __restrict__ alpha, const float* __restrict__ beta,
    float* __restrict__ out)
{
    const int idx = blockIdx.x * TPB + threadIdx.x;   // 0 .. B*H*N-1
    const int bh = idx >> 11;
    const int n  = idx & (N_TOK - 1);
    const int h  = bh & (N_HEAD - 1);
    const int b  = bh >> 4;

    // Sum the KSPLIT partial accumulators.
    float y[7]; float l = 0.0f;
    #pragma unroll
    for (int i = 0; i < 7; i++) y[i] = 0.0f;
    #pragma unroll
    for (int ks = 0; ks < KSPLIT; ks++) {
        const u64* p = g_part + ((((size_t)ks * (N_BATCH * N_HEAD) + bh) * N_TOK + n) << 2);
        ulonglong2 w0 = *(const ulonglong2*)(p);
        ulonglong2 w1 = *(const ulonglong2*)(p + 2);
        float t0, t1;
        f2unpack(w0.x, t0, t1); y[0] += t0; y[1] += t1;
        f2unpack(w0.y, t0, t1); y[2] += t0; y[3] += t1;
        f2unpack(w1.x, t0, t1); y[4] += t0; y[5] += t1;
        f2unpack(w1.y, t0, t1); y[6] += t0; l    += t1;
    }
    float rinv = 1.0f / l;
    #pragma unroll
    for (int i = 0; i < 7; i++) y[i] *= rinv;

    // Load q (raw imag parts) + real component.
    const float* obase = o + ((size_t)b * N_TOK) * DMODEL + h * 8;
    float4 q0 = *(const float4*)(obase + (size_t)n * DMODEL);
    float4 q1 = *(const float4*)(obase + (size_t)n * DMODEL + 4);
    float real = q0.x;
    float qo[7] = {q0.y, q0.z, q0.w, q1.x, q1.y, q1.z, q1.w};

    // Octonion cross product c = qo x y.
    float c[7];
    #pragma unroll
    for (int i = 0; i < 7; i++) c[i] = 0.0f;
    const int FI[7] = {0, 0, 0, 1, 1, 2, 2};
    const int FJ[7] = {1, 3, 6, 3, 4, 3, 5};
    const int FK[7] = {2, 4, 5, 5, 6, 6, 4};
    #pragma unroll
    for (int t = 0; t < 7; t++) {
        int i = FI[t], j = FJ[t], k = FK[t];
        c[k] += qo[i] * y[j] - qo[j] * y[i];
        c[i] += qo[j] * y[k] - qo[k] * y[j];
        c[j] += qo[k] * y[i] - qo[i] * y[k];
    }

    float av = 1.0f / (1.0f + __expf(-alpha[h]));
    float bv = tanhf(beta[h]);

    float im[7];
    float ns = real * real;
    #pragma unroll
    for (int i = 0; i < 7; i++) {
        im[i] = av * y[i] + bv * c[i];
        ns += im[i] * im[i];
    }
    float inv = 1.0f / fmaxf(sqrtf(ns), 1e-12f);

    float* op = out + ((size_t)(b * N_TOK + n)) * DMODEL + h * 8;
    *(float4*)(op)     = make_float4(real * inv, im[0] * inv, im[1] * inv, im[2] * inv);
    *(float4*)(op + 4) = make_float4(im[3] * inv, im[4] * inv, im[5] * inv, im[6] * inv);
}

extern "C" void kernel_launch(void* const* d_in, const int* in_sizes, int n_in,
                              void* d_out, int out_size) {
    const float* o     = (const float*)d_in[0];
    const float* mix   = (const float*)d_in[1];
    const float* alpha = (const float*)d_in[2];
    const float* beta  = (const float*)d_in[3];
    float* out = (float*)d_out;
    (void)in_sizes; (void)n_in; (void)out_size;

    dim3 grid1(N_TOK / TPB, N_BATCH * N_HEAD, KSPLIT);   // (8, 32, 4) = 1024 CTAs
    g2_attn_partial<<<grid1, TPB>>>(o, mix);

    int total = N_BATCH * N_HEAD * N_TOK;                // 65536 queries
    g2_attn_combine<<<total / TPB, TPB>>>(o, alpha, beta, out);
}

// round 3
// speedup vs baseline: 1.3767x; 1.1091x over previous
#include <cuda_runtime.h>

// G2InvariantAttention — GB300 sm_103a — Round 3:
//   * key-pair packed inner loop: f32x2 lanes carry TWO KEYS, so the score
//     chain computes both dot products at once (7 FMA / 2 keys, no horizontal
//     add) and accumulation stays packed (7 FMA + 1 packed add / 2 keys).
//     FMA-pipe ops: 9/key -> 7.5/key.
//   * KSPLIT=8 for finer tail; combine uses 8 lanes/query + shfl reduction
//     to fix the latency-bound combine (was 3.5 warps/SMSP).
// Exact math simplifications unchanged: oct_cross(k,k)=0, v==k, scale folded
// into q, no max-subtraction (logits bounded), linear partial combination.

#define N_TOK   2048
#define N_HEAD  16
#define N_BATCH 2
#define DMODEL  128
#define TPB     256
#define KSPLIT  8
#define KCHUNK  (N_TOK / KSPLIT)      // 256 keys per CTA
#define NPAIR   (KCHUNK / 2)          // 128 key pairs

typedef unsigned long long u64;

// Scratch: [KSPLIT][B*H][N][8 floats] = 16 MB
__device__ float g_part[(size_t)KSPLIT * N_BATCH * N_HEAD * N_TOK * 8];

__device__ __forceinline__ u64 f2pack(float lo, float hi) {
    u64 r; asm("mov.b64 %0,{%1,%2};" : "=l"(r) : "f"(lo), "f"(hi)); return r;
}
__device__ __forceinline__ void f2unpack(u64 v, float& lo, float& hi) {
    asm("mov.b64 {%0,%1},%2;" : "=f"(lo), "=f"(hi) : "l"(v));
}
__device__ __forceinline__ u64 f2fma(u64 a, u64 b, u64 c) {
    u64 d; asm("fma.rn.f32x2 %0,%1,%2,%3;" : "=l"(d) : "l"(a), "l"(b), "l"(c)); return d;
}
__device__ __forceinline__ u64 f2mul(u64 a, u64 b) {
    u64 d; asm("mul.rn.f32x2 %0,%1,%2;" : "=l"(d) : "l"(a), "l"(b)); return d;
}
__device__ __forceinline__ u64 f2add(u64 a, u64 b) {
    u64 d; asm("add.rn.f32x2 %0,%1,%2;" : "=l"(d) : "l"(a), "l"(b)); return d;
}
__device__ __forceinline__ float fast_ex2(float x) {
    float r; asm("ex2.approx.f32 %0,%1;" : "=f"(r) : "f"(x)); return r;
}

// ---------------- Kernel 1: partial attention over a 256-key slice ----------
__global__ void __launch_bounds__(TPB, 4) g2_attn_partial(
    const float* __restrict__ o, const float* __restrict__ mix)
{
    // Pair-major layout: sP[pair][i][parity], i = 0..6 dims, slot 7 = pad.
    __shared__ float sP[NPAIR * 16];   // 8 KB

    const int bh  = blockIdx.y;
    const int h   = bh & (N_HEAD - 1);
    const int b   = bh >> 4;
    const int ks  = blockIdx.z;
    const int tid = threadIdx.x;
    const float* obase = o + ((size_t)b * N_TOK) * DMODEL + h * 8;

    // Each thread loads one key of this CTA's slice, scatters into pair layout.
    {
        int j  = tid;                       // 0..255 == KCHUNK
        int jg = ks * KCHUNK + j;
        float4 v0 = *(const float4*)(obase + (size_t)jg * DMODEL);      // real,i0,i1,i2
        float4 v1 = *(const float4*)(obase + (size_t)jg * DMODEL + 4);  // i3..i6
        float* dst = sP + (j >> 1) * 16 + (j & 1);
        dst[0]  = v0.y;  dst[2]  = v0.z;  dst[4]  = v0.w;  dst[6]  = v1.x;
        dst[8]  = v1.y;  dst[10] = v1.z;  dst[12] = v1.w;  dst[14] = 0.0f;  // pad
    }
    __syncthreads();

    const int n = blockIdx.x * TPB + tid;

    // w_k = sigmoid(m0-m1); fold w_k * log2e / sqrt(7) into q.
    float m0 = mix[2 * h], m1 = mix[2 * h + 1];
    float wk = 1.0f / (1.0f + __expf(m1 - m0));
    const float coef = wk * 1.4426950408889634f * 0.3779644730092272f;

    float4 q0 = *(const float4*)(obase + (size_t)n * DMODEL);
    float4 q1 = *(const float4*)(obase + (size_t)n * DMODEL + 4);
    // Duplicated scaled query components (one per dim, both lanes equal).
    u64 qd0 = f2pack(q0.y * coef, q0.y * coef);
    u64 qd1 = f2pack(q0.z * coef, q0.z * coef);
    u64 qd2 = f2pack(q0.w * coef, q0.w * coef);
    u64 qd3 = f2pack(q1.x * coef, q1.x * coef);
    u64 qd4 = f2pack(q1.y * coef, q1.y * coef);
    u64 qd5 = f2pack(q1.z * coef, q1.z * coef);
    u64 qd6 = f2pack(q1.w * coef, q1.w * coef);

    u64 a0 = 0ULL, a1 = 0ULL, a2 = 0ULL, a3 = 0ULL, a4 = 0ULL, a5 = 0ULL, a6 = 0ULL;
    u64 l2 = 0ULL;   // (sum e over even keys, sum e over odd keys)

    unsigned sbase;
    asm("{ .reg .u64 t; cvta.to.shared.u64 t, %1; cvt.u32.u64 %0, t; }"
        : "=r"(sbase) : "l"(sP));

    unsigned addr = sbase;
    #pragma unroll 2
    for (int p = 0; p < NPAIR; p++, addr += 64) {
        u64 P0, P1, P2, P3, P4, P5, P6, P7;
        asm("ld.shared.v2.b64 {%0,%1},[%2];" : "=l"(P0), "=l"(P1) : "r"(addr));
        asm("ld.shared.v2.b64 {%0,%1},[%2];" : "=l"(P2), "=l"(P3) : "r"(addr + 16));
        asm("ld.shared.v2.b64 {%0,%1},[%2];" : "=l"(P4), "=l"(P5) : "r"(addr + 32));
        asm("ld.shared.v2.b64 {%0,%1},[%2];" : "=l"(P6), "=l"(P7) : "r"(addr + 48));
        (void)P7;
        // Both keys' scores in the two lanes.
        u64 s = f2mul(qd0, P0);
        s = f2fma(qd1, P1, s);
        s = f2fma(qd2, P2, s);
        s = f2fma(qd3, P3, s);
        s = f2fma(qd4, P4, s);
        s = f2fma(qd5, P5, s);
        s = f2fma(qd6, P6, s);
        float sa, sb; f2unpack(s, sa, sb);
        float ea = fast_ex2(sa);
        float eb = fast_ex2(sb);
        u64 e2 = f2pack(ea, eb);
        a0 = f2fma(P0, e2, a0);
        a1 = f2fma(P1, e2, a1);
        a2 = f2fma(P2, e2, a2);
        a3 = f2fma(P3, e2, a3);
        a4 = f2fma(P4, e2, a4);
        a5 = f2fma(P5, e2, a5);
        a6 = f2fma(P6, e2, a6);
        l2 = f2add(l2, e2);
    }

    // Horizontal sums -> (y0..y6, l), write 32B partial.
    float lo, hi, y[8];
    f2unpack(a0, lo, hi); y[0] = lo + hi;
    f2unpack(a1, lo, hi); y[1] = lo + hi;
    f2unpack(a2, lo, hi); y[2] = lo + hi;
    f2unpack(a3, lo, hi); y[3] = lo + hi;
    f2unpack(a4, lo, hi); y[4] = lo + hi;
    f2unpack(a5, lo, hi); y[5] = lo + hi;
    f2unpack(a6, lo, hi); y[6] = lo + hi;
    f2unpack(l2, lo, hi); y[7] = lo + hi;

    float* p = g_part + ((((size_t)ks * (N_BATCH * N_HEAD) + bh) * N_TOK + n) << 3);
    *(float4*)(p)     = make_float4(y[0], y[1], y[2], y[3]);
    *(float4*)(p + 4) = make_float4(y[4], y[5], y[6], y[7]);
}

// ---------------- Kernel 2: combine (8 lanes per query) + epilogue ----------
__global__ void __launch_bounds__(TPB) g2_attn_combine(
    const float* __restrict__ o,
    const float* __restrict__ alpha, const float* __restrict__ beta,
    float* __restrict__ out)
{
    const int gidx = blockIdx.x * TPB + threadIdx.x;
    const int qi   = gidx >> 3;            // query index 0..65535
    const int ks   = gidx & 7;             // split handled by this lane
    const int bh   = qi >> 11;
    const int n    = qi & (N_TOK - 1);
    const int h    = bh & (N_HEAD - 1);
    const int b    = bh >> 4;

    const float* p = g_part + ((((size_t)ks * (N_BATCH * N_HEAD) + bh) * N_TOK + n) << 3);
    float4 w0 = *(const float4*)(p);
    float4 w1 = *(const float4*)(p + 4);
    float y[7] = {w0.x, w0.y, w0.z, w0.w, w1.x, w1.y, w1.z};
    float l = w1.w;

    // Reduce across the 8 lanes that share this query.
    #pragma unroll
    for (int m = 1; m < 8; m <<= 1) {
        #pragma unroll
        for (int i = 0; i < 7; i++) y[i] += __shfl_xor_sync(0xffffffffu, y[i], m);
        l += __shfl_xor_sync(0xffffffffu, l, m);
    }

    if (ks != 0) return;

    float rinv = 1.0f / l;
    #pragma unroll
    for (int i = 0; i < 7; i++) y[i] *= rinv;

    const float* obase = o + ((size_t)b * N_TOK) * DMODEL + h * 8;
    float4 q0 = *(const float4*)(obase + (size_t)n * DMODEL);
    float4 q1 = *(const float4*)(obase + (size_t)n * DMODEL + 4);
    float real = q0.x;
    float qo[7] = {q0.y, q0.z, q0.w, q1.x, q1.y, q1.z, q1.w};

    // Octonion cross product c = qo x y.
    float c[7];
    #pragma unroll
    for (int i = 0; i < 7; i++) c[i] = 0.0f;
    const int FI[7] = {0, 0, 0, 1, 1, 2, 2};
    const int FJ[7] = {1, 3, 6, 3, 4, 3, 5};
    const int FK[7] = {2, 4, 5, 5, 6, 6, 4};
    #pragma unroll
    for (int t = 0; t < 7; t++) {
        int i = FI[t], j = FJ[t], k = FK[t];
        c[k] += qo[i] * y[j] - qo[j] * y[i];
        c[i] += qo[j] * y[k] - qo[k] * y[j];
        c[j] += qo[k] * y[i] - qo[i] * y[k];
    }

    float av = 1.0f / (1.0f + __expf(-alpha[h]));
    float bv = tanhf(beta[h]);

    float im[7];
    float ns = real * real;
    #pragma unroll
    for (int i = 0; i < 7; i++) {
        im[i] = av * y[i] + bv * c[i];
        ns += im[i] * im[i];
    }
    float inv = 1.0f / fmaxf(sqrtf(ns), 1e-12f);

    float* op = out + ((size_t)(b * N_TOK + n)) * DMODEL + h * 8;
    *(float4*)(op)     = make_float4(real * inv, im[0] * inv, im[1] * inv, im[2] * inv);
    *(float4*)(op + 4) = make_float4(im[3] * inv, im[4] * inv, im[5] * inv, im[6] * inv);
}

extern "C" void kernel_launch(void* const* d_in, const int* in_sizes, int n_in,
                              void* d_out, int out_size) {
    const float* o     = (const float*)d_in[0];
    const float* mix   = (const float*)d_in[1];
    const float* alpha = (const float*)d_in[2];
    const float* beta  = (const float*)d_in[3];
    float* out = (float*)d_out;
    (void)in_sizes; (void)n_in; (void)out_size;

    dim3 grid1(N_TOK / TPB, N_BATCH * N_HEAD, KSPLIT);   // (8, 32, 8) = 2048 CTAs
    g2_attn_partial<<<grid1, TPB>>>(o, mix);

    int total = N_BATCH * N_HEAD * N_TOK * KSPLIT;       // 524288 lanes
    g2_attn_combine<<<total / TPB, TPB>>>(o, alpha, beta, out);
}